// round 4
// baseline (speedup 1.0000x reference)
#include <cuda_runtime.h>

// KPN 5x5 per-pixel convolution, float4-vectorized, single-wave persistent grid.
// frames: (B=16, N=1, C=3, H=256, W=256) float32
// core:   (B=16, N=1, 25,  C=3, H=256, W=256) float32
// out:    (B=16, C=3, H=256, W=256) float32
//
// pred[b,c,h,w] = sum_{i,j} core[b,0,i*5+j,c,h,w] * frame_pad[b,0,c,h+i,w+j]
// zero padding 2 each spatial side (rate=1).

#define KK 5
#define PAD 2
#define WID 256
#define HEI 256
#define CH 3
#define BATCH 16
#define TILE_H 4
#define TX 64                       // threads in x; each covers 4 pixels
#define SW (WID + 2 * PAD)          // 260 floats per smem row (1040B, 16B-aligned)

#define N_TILES ((HEI / TILE_H) * CH * BATCH)   // 64*3*16 = 3072
#define GRID 768                                 // 3072 / 768 = 4 tiles per CTA,
                                                 // fits in ONE wave (<= 148*6 slots)

__global__ __launch_bounds__(TX * TILE_H, 6)
void kpn_conv_kernel(const float* __restrict__ frames,
                     const float* __restrict__ core,
                     float* __restrict__ out) {
    const size_t plane   = (size_t)HEI * WID;                 // 65536
    const size_t cstride = (size_t)CH * plane;                // tap stride in core

    __shared__ __align__(16) float tile_s[TILE_H + 2 * PAD][SW]; // 8 x 260 = 8320 B

    const int tid      = threadIdx.y * TX + threadIdx.x;      // 0..255
    const int nthreads = TX * TILE_H;                         // 256
    const int total    = (TILE_H + 2 * PAD) * SW;             // 2080

    const int w4 = threadIdx.x * 4;
    const int ty = threadIdx.y;

    // Grid-stride over all (tile, channel, batch) work items: exactly 4 per CTA.
#pragma unroll 1
    for (int item = blockIdx.x; item < N_TILES; item += GRID) {
        // Decode: item = ((b * CH) + c) * (HEI/TILE_H) + tile
        const int tile = item & 63;               // HEI/TILE_H == 64
        const int bc   = item >> 6;               // b * CH + c
        const int c    = bc % CH;
        const int b    = bc / CH;
        const int h0   = tile * TILE_H;

        const float* fbase = frames + ((size_t)b * CH + c) * plane;
        const float* cbase = core   + ((size_t)b * 25 * CH + c) * plane;

        __syncthreads();   // previous tile's compute done before restaging

        // ---- Stage zero-padded frame tile into shared memory ----
        for (int k = tid; k < total; k += nthreads) {
            const int r  = k / SW;
            const int cc = k - r * SW;
            const int gh = h0 - PAD + r;
            const int gw = cc - PAD;
            float v = 0.0f;
            if (gh >= 0 && gh < HEI && gw >= 0 && gw < WID)
                v = fbase[(size_t)gh * WID + gw];
            tile_s[r][cc] = v;
        }
        __syncthreads();

        // ---- Each thread computes 4 consecutive output pixels ----
        const int h = h0 + ty;
        const float* crow = cbase + (size_t)h * WID + w4;

        float4 acc = make_float4(0.f, 0.f, 0.f, 0.f);

        // i-loop NOT unrolled: keeps front-batched LDG run ~5, avoiding the
        // cross-CTA L1tex-queue contention / CTA-spread regime.
#pragma unroll 1
        for (int i = 0; i < KK; i++) {
            const float4 s0 = *reinterpret_cast<const float4*>(&tile_s[ty + i][w4]);
            const float4 s1 = *reinterpret_cast<const float4*>(&tile_s[ty + i][w4 + 4]);
            const float s[8] = {s0.x, s0.y, s0.z, s0.w, s1.x, s1.y, s1.z, s1.w};

            const float* ci = crow + (size_t)(i * KK) * cstride;
#pragma unroll
            for (int j = 0; j < KK; j++) {
                // core is read exactly once — streaming, evict-first
                const float4 cv =
                    __ldcs(reinterpret_cast<const float4*>(ci + (size_t)j * cstride));
                acc.x = fmaf(cv.x, s[j + 0], acc.x);
                acc.y = fmaf(cv.y, s[j + 1], acc.y);
                acc.z = fmaf(cv.z, s[j + 2], acc.z);
                acc.w = fmaf(cv.w, s[j + 3], acc.w);
            }
        }

        float* orow = out + ((size_t)b * CH + c) * plane + (size_t)h * WID + w4;
        __stcs(reinterpret_cast<float4*>(orow), acc);
    }
}

extern "C" void kernel_launch(void* const* d_in, const int* in_sizes, int n_in,
                              void* d_out, int out_size) {
    const float* frames = (const float*)d_in[0];
    const float* core   = (const float*)d_in[1];
    // d_in[2] = rate (scalar, fixed 1 for this instance)
    float* out = (float*)d_out;

    dim3 block(TX, TILE_H, 1);              // 256 threads
    dim3 grid(GRID, 1, 1);                  // 768 CTAs = one full wave, 4 tiles each
    kpn_conv_kernel<<<grid, block>>>(frames, core, out);
}

// round 5
// speedup vs baseline: 1.2999x; 1.2999x over previous
#include <cuda_runtime.h>

// KPN 5x5 per-pixel convolution, float4-vectorized (R3 structure, occ=8).
// frames: (B=16, N=1, C=3, H=256, W=256) float32
// core:   (B=16, N=1, 25,  C=3, H=256, W=256) float32
// out:    (B=16, C=3, H=256, W=256) float32
//
// pred[b,c,h,w] = sum_{i,j} core[b,0,i*5+j,c,h,w] * frame_pad[b,0,c,h+i,w+j]
// zero padding 2 each spatial side (rate=1).

#define KK 5
#define PAD 2
#define WID 256
#define HEI 256
#define CH 3
#define TILE_H 4
#define TX 64                       // threads in x; each covers 4 pixels
#define SW (WID + 2 * PAD)          // 260 floats per smem row (1040B, 16B-aligned)

__global__ __launch_bounds__(TX * TILE_H, 8)
void kpn_conv_kernel(const float* __restrict__ frames,
                     const float* __restrict__ core,
                     float* __restrict__ out) {
    const int tile = blockIdx.x;    // H / TILE_H
    const int c    = blockIdx.y;    // channel
    const int b    = blockIdx.z;    // batch
    const int h0   = tile * TILE_H;

    const size_t plane   = (size_t)HEI * WID;                 // 65536
    const float* fbase   = frames + ((size_t)b * CH + c) * plane;
    const float* cbase   = core   + ((size_t)b * 25 * CH + c) * plane;
    const size_t cstride = (size_t)CH * plane;                // tap stride

    __shared__ __align__(16) float tile_s[TILE_H + 2 * PAD][SW]; // 8 x 260 = 8320 B

    // ---- Stage zero-padded frame tile into shared memory ----
    const int tid      = threadIdx.y * TX + threadIdx.x;      // 0..255
    const int nthreads = TX * TILE_H;                         // 256
    const int total    = (TILE_H + 2 * PAD) * SW;             // 2080
    for (int k = tid; k < total; k += nthreads) {
        const int r  = k / SW;
        const int cc = k - r * SW;
        const int gh = h0 - PAD + r;
        const int gw = cc - PAD;
        float v = 0.0f;
        if (gh >= 0 && gh < HEI && gw >= 0 && gw < WID)
            v = __ldg(&fbase[(size_t)gh * WID + gw]);
        tile_s[r][cc] = v;
    }
    __syncthreads();

    // ---- Each thread computes 4 consecutive output pixels ----
    const int w4 = threadIdx.x * 4;
    const int ty = threadIdx.y;
    const int h  = h0 + ty;

    const float* crow = cbase + (size_t)h * WID + w4;

    float4 acc = make_float4(0.f, 0.f, 0.f, 0.f);

    // i-loop NOT unrolled: keeps the front-batched LDG run at ~5 instead of 25,
    // avoiding the cross-CTA L1tex-queue contention / CTA-spread regime.
#pragma unroll 1
    for (int i = 0; i < KK; i++) {
        const float4 s0 = *reinterpret_cast<const float4*>(&tile_s[ty + i][w4]);
        const float4 s1 = *reinterpret_cast<const float4*>(&tile_s[ty + i][w4 + 4]);
        const float s[8] = {s0.x, s0.y, s0.z, s0.w, s1.x, s1.y, s1.z, s1.w};

        const float* ci = crow + (size_t)(i * KK) * cstride;
#pragma unroll
        for (int j = 0; j < KK; j++) {
            // core is read exactly once — streaming, evict-first
            const float4 cv =
                __ldcs(reinterpret_cast<const float4*>(ci + (size_t)j * cstride));
            acc.x = fmaf(cv.x, s[j + 0], acc.x);
            acc.y = fmaf(cv.y, s[j + 1], acc.y);
            acc.z = fmaf(cv.z, s[j + 2], acc.z);
            acc.w = fmaf(cv.w, s[j + 3], acc.w);
        }
    }

    float* orow = out + ((size_t)b * CH + c) * plane + (size_t)h * WID + w4;
    __stcs(reinterpret_cast<float4*>(orow), acc);
}

extern "C" void kernel_launch(void* const* d_in, const int* in_sizes, int n_in,
                              void* d_out, int out_size) {
    const float* frames = (const float*)d_in[0];
    const float* core   = (const float*)d_in[1];
    // d_in[2] = rate (scalar, fixed 1 for this instance)
    float* out = (float*)d_out;

    dim3 block(TX, TILE_H, 1);              // 256 threads
    dim3 grid(HEI / TILE_H, CH, 16);        // 64 x 3 x 16 = 3072 CTAs
    kpn_conv_kernel<<<grid, block>>>(frames, core, out);
}

// round 6
// speedup vs baseline: 1.3030x; 1.0024x over previous
#include <cuda_runtime.h>

// KPN 5x5 per-pixel convolution — barrier-free, smem-free.
// frames: (B=16, N=1, C=3, H=256, W=256) float32   (L2-resident, 25x reuse via L1/L2)
// core:   (B=16, N=1, 25,  C=3, H=256, W=256) float32 (streamed once, evict-first)
// out:    (B=16, C=3, H=256, W=256) float32
//
// pred[b,c,h,w] = sum_{i,j} core[b,0,i*5+j,c,h,w] * frame_pad[b,0,c,h+i,w+j]
// zero padding 2 each side (rate=1).

#define KK 5
#define PAD 2
#define WID 256
#define HEI 256
#define CH 3
#define TILE_H 4
#define TX 64                       // threads in x; each covers 4 pixels

__global__ __launch_bounds__(TX * TILE_H, 6)
void kpn_conv_kernel(const float* __restrict__ frames,
                     const float* __restrict__ core,
                     float* __restrict__ out) {
    const int tile = blockIdx.x;    // H / TILE_H
    const int c    = blockIdx.y;    // channel
    const int b    = blockIdx.z;    // batch

    const size_t plane   = (size_t)HEI * WID;                 // 65536
    const float* fbase   = frames + ((size_t)b * CH + c) * plane;
    const float* cbase   = core   + ((size_t)b * 25 * CH + c) * plane;
    const size_t cstride = (size_t)CH * plane;                // tap stride

    const int w4 = threadIdx.x * 4;                           // first pixel col
    const int h  = tile * TILE_H + threadIdx.y;               // output row

    const float* crow = cbase + (size_t)h * WID + w4;

    const float4 f4z = make_float4(0.f, 0.f, 0.f, 0.f);
    float4 acc = f4z;

    // i-loop NOT unrolled: keeps front-batched LDG run short (3 frame + 5 core),
    // avoiding the cross-CTA L1tex-queue contention regime. No smem, no barriers:
    // every warp is an uninterrupted LDG->FMA stream.
#pragma unroll 1
    for (int i = 0; i < KK; i++) {
        const int gh = h - PAD + i;
        const bool vh = ((unsigned)gh < (unsigned)HEI);
        const float* frow = fbase + (size_t)gh * WID + w4;

        // 12-float window: cols w4-4 .. w4+7 (aligned LDG.128, edge-predicated)
        const float4 fa = (vh && w4 != 0)
                              ? __ldg(reinterpret_cast<const float4*>(frow - 4)) : f4z;
        const float4 fb = vh ? __ldg(reinterpret_cast<const float4*>(frow))      : f4z;
        const float4 fc = (vh && w4 != WID - 4)
                              ? __ldg(reinterpret_cast<const float4*>(frow + 4)) : f4z;
        const float s[12] = {fa.x, fa.y, fa.z, fa.w,
                             fb.x, fb.y, fb.z, fb.w,
                             fc.x, fc.y, fc.z, fc.w};

        const float* ci = crow + (size_t)(i * KK) * cstride;
#pragma unroll
        for (int j = 0; j < KK; j++) {
            // core read exactly once — streaming, evict-first
            const float4 cv =
                __ldcs(reinterpret_cast<const float4*>(ci + (size_t)j * cstride));
            // pixel p (col w4+p), tap j -> frame col w4+p+j-2 = s[p+j+2]
            acc.x = fmaf(cv.x, s[j + 2], acc.x);
            acc.y = fmaf(cv.y, s[j + 3], acc.y);
            acc.z = fmaf(cv.z, s[j + 4], acc.z);
            acc.w = fmaf(cv.w, s[j + 5], acc.w);
        }
    }

    float* orow = out + ((size_t)b * CH + c) * plane + (size_t)h * WID + w4;
    __stcs(reinterpret_cast<float4*>(orow), acc);
}

extern "C" void kernel_launch(void* const* d_in, const int* in_sizes, int n_in,
                              void* d_out, int out_size) {
    const float* frames = (const float*)d_in[0];
    const float* core   = (const float*)d_in[1];
    // d_in[2] = rate (scalar, fixed 1 for this instance)
    float* out = (float*)d_out;

    dim3 block(TX, TILE_H, 1);              // 256 threads
    dim3 grid(HEI / TILE_H, CH, 16);        // 64 x 3 x 16 = 3072 CTAs
    kpn_conv_kernel<<<grid, block>>>(frames, core, out);
}